// round 2
// baseline (speedup 1.0000x reference)
#include <cuda_runtime.h>

#define NB   128   // batch
#define NN0  128
#define NN1  128
#define ND   32
#define NP   (NN0*NN1)            // 16384 pairs
#define PAIRS_PER_CTA 128
#define NCHUNK (NP/PAIRS_PER_CTA) // 128
#define GROUPS 4
#define THREADS 512
#define PSTRIDE 33                // 32 num + 1 den per batch
#define REDPAD  34                // padded stride in smem reduce buffer

// __device__ scratch (allocation-free rule: static device globals)
__device__ float g_p2[NP*ND];
__device__ float g_p1[NP*ND];
__device__ float g_pk[NP*ND];
__device__ float g_pc[NP*ND];
__device__ float g_p0[NP];
__device__ float g_partial[NCHUNK*NB*PSTRIDE];

// ---------------------------------------------------------------------------
// Kernel 1: per-pair coefficients (depends only on t, Mu0, Mu1, S0, S1)
// logw(b,ij) = sum_n p2*x^2 + p1*x  + p0      (p2=-0.5/Sigma, p1=mut/Sigma)
// U_n        = K*x + c,  c = v - K*mut
// ---------------------------------------------------------------------------
__global__ void precompute_kernel(const float* __restrict__ t_ptr,
                                  const float* __restrict__ Mu0,
                                  const float* __restrict__ Mu1,
                                  const float* __restrict__ S0,
                                  const float* __restrict__ S1)
{
    const int j  = threadIdx.x;   // N1 index
    const int i  = blockIdx.x;    // N0 index
    const int ij = i*NN1 + j;

    const float t   = t_ptr[0];
    const float omt = 1.0f - t;
    const float e2  = 0.25f;      // eps^2, eps=0.5
    const float e4  = 0.0625f;    // eps^4

    float p0acc = 0.0f;
    #pragma unroll
    for (int n = 0; n < ND; n++) {
        const float s0 = S0[i*ND + n];
        const float s1 = S1[j*ND + n];
        const float Ds = sqrtf(4.0f*s0*s1 + e4);
        const float Cs = 0.5f*(Ds - e2);
        const float Sigma = omt*omt*s0 + t*t*s1 + 2.0f*t*omt*Cs + e2*t*omt;
        const float Pt = t*s1 + omt*Cs;
        const float Qt = omt*s0 + t*Cs;
        const float St = Pt - Qt - e2*t;

        const float mu0 = Mu0[i*ND + n];
        const float mu1 = Mu1[j*ND + n];
        const float mut = omt*mu0 + t*mu1;
        const float v   = mu1 - mu0;

        const float inv = 1.0f / Sigma;
        const float K   = St * inv;
        const float a   = -0.5f * inv;

        g_p2[ij*ND + n] = a;
        g_p1[ij*ND + n] = inv * mut;     // = -2*a*mut
        g_pk[ij*ND + n] = K;
        g_pc[ij*ND + n] = v - K*mut;

        p0acc += a*mut*mut - 0.5f*logf(Sigma);
    }
    g_p0[ij] = p0acc;
}

// ---------------------------------------------------------------------------
// Kernel 2: main accumulation. CTA = 128 pairs; thread = (batch, pair-group).
// Coefficients staged in SMEM (broadcast reads), x in registers, 33 register
// accumulators per thread, fixed-order 4-way group reduce in SMEM.
// ---------------------------------------------------------------------------
__global__ __launch_bounds__(THREADS, 1)
void main_kernel(const float* __restrict__ X, const float* __restrict__ Lam)
{
    extern __shared__ float smem[];
    float* s_p2  = smem;                          // 4096
    float* s_p1  = s_p2 + PAIRS_PER_CTA*ND;       // 4096
    float* s_pk  = s_p1 + PAIRS_PER_CTA*ND;       // 4096
    float* s_pc  = s_pk + PAIRS_PER_CTA*ND;       // 4096
    float* s_p0  = s_pc + PAIRS_PER_CTA*ND;       // 128
    float* s_lam = s_p0 + PAIRS_PER_CTA;          // 128
    float* s_red = s_lam + PAIRS_PER_CTA;         // GROUPS*NB*REDPAD = 17408

    const int tid      = threadIdx.x;
    const int chunk    = blockIdx.x;
    const int pairBase = chunk * PAIRS_PER_CTA;

    // cooperative staged load of coefficient tables (float4, coalesced)
    const int NV = PAIRS_PER_CTA*ND/4;   // 1024 float4 per array
    {
        const float4* gp2 = (const float4*)(g_p2 + (size_t)pairBase*ND);
        const float4* gp1 = (const float4*)(g_p1 + (size_t)pairBase*ND);
        const float4* gpk = (const float4*)(g_pk + (size_t)pairBase*ND);
        const float4* gpc = (const float4*)(g_pc + (size_t)pairBase*ND);
        float4* sp2 = (float4*)s_p2;
        float4* sp1 = (float4*)s_p1;
        float4* spk = (float4*)s_pk;
        float4* spc = (float4*)s_pc;
        for (int k = tid; k < NV; k += THREADS) {
            sp2[k] = gp2[k];
            sp1[k] = gp1[k];
            spk[k] = gpk[k];
            spc[k] = gpc[k];
        }
    }
    if (tid < PAIRS_PER_CTA) {
        s_p0[tid]  = g_p0[pairBase + tid];
        s_lam[tid] = Lam[pairBase + tid];
    }

    const int b = tid & (NB-1);     // batch handled by this thread
    const int g = tid >> 7;         // pair group (0..3)

    float4 x[8];
    {
        const float4* xg = (const float4*)(X + b*ND);
        #pragma unroll
        for (int q = 0; q < 8; q++) x[q] = __ldg(xg + q);
    }
    __syncthreads();

    float den = 0.0f;
    float4 num[8];
    #pragma unroll
    for (int q = 0; q < 8; q++) num[q] = make_float4(0.f,0.f,0.f,0.f);

    const int pStart = g * (PAIRS_PER_CTA/GROUPS);
    #pragma unroll 1
    for (int pp = 0; pp < PAIRS_PER_CTA/GROUPS; pp++) {
        const int p = pStart + pp;
        const float4* a4 = (const float4*)(s_p2 + p*ND);
        const float4* b4 = (const float4*)(s_p1 + p*ND);

        float lw0 = s_p0[p], lw1 = 0.f, lw2 = 0.f, lw3 = 0.f;
        #pragma unroll
        for (int q = 0; q < 8; q++) {
            const float4 av = a4[q];
            const float4 bv = b4[q];
            lw0 = fmaf(fmaf(av.x, x[q].x, bv.x), x[q].x, lw0);
            lw1 = fmaf(fmaf(av.y, x[q].y, bv.y), x[q].y, lw1);
            lw2 = fmaf(fmaf(av.z, x[q].z, bv.z), x[q].z, lw2);
            lw3 = fmaf(fmaf(av.w, x[q].w, bv.w), x[q].w, lw3);
        }
        float logw = (lw0 + lw1) + (lw2 + lw3);
        logw = fminf(fmaxf(logw, -50.0f), 50.0f);
        const float w = __expf(logw) * s_lam[p];
        den += w;

        const float4* k4 = (const float4*)(s_pk + p*ND);
        const float4* c4 = (const float4*)(s_pc + p*ND);
        #pragma unroll
        for (int q = 0; q < 8; q++) {
            const float4 kv = k4[q];
            const float4 cv = c4[q];
            num[q].x = fmaf(fmaf(kv.x, x[q].x, cv.x), w, num[q].x);
            num[q].y = fmaf(fmaf(kv.y, x[q].y, cv.y), w, num[q].y);
            num[q].z = fmaf(fmaf(kv.z, x[q].z, cv.z), w, num[q].z);
            num[q].w = fmaf(fmaf(kv.w, x[q].w, cv.w), w, num[q].w);
        }
    }

    // write per-(group,batch) partials to smem
    {
        float* my = s_red + (g*NB + b)*REDPAD;
        #pragma unroll
        for (int q = 0; q < 8; q++) {
            my[4*q+0] = num[q].x;
            my[4*q+1] = num[q].y;
            my[4*q+2] = num[q].z;
            my[4*q+3] = num[q].w;
        }
        my[32] = den;
    }
    __syncthreads();

    // fixed-order sum over the 4 groups, write chunk partial to global
    for (int k = tid; k < NB*PSTRIDE; k += THREADS) {
        const int bb = k / PSTRIDE;
        const int n  = k - bb*PSTRIDE;
        const float v = (s_red[(0*NB+bb)*REDPAD + n] + s_red[(1*NB+bb)*REDPAD + n])
                      + (s_red[(2*NB+bb)*REDPAD + n] + s_red[(3*NB+bb)*REDPAD + n]);
        g_partial[(size_t)chunk*NB*PSTRIDE + k] = v;
    }
}

// ---------------------------------------------------------------------------
// Kernel 3: reduce 128 chunk partials, divide num/den
// ---------------------------------------------------------------------------
__global__ void reduce_kernel(float* __restrict__ out)
{
    const int idx = blockIdx.x * blockDim.x + threadIdx.x;  // 0..4095
    if (idx >= NB*ND) return;
    const int b = idx / ND;
    const int n = idx - b*ND;

    float num = 0.0f, den = 0.0f;
    #pragma unroll 4
    for (int c = 0; c < NCHUNK; c++) {
        const float* base = g_partial + (size_t)c*NB*PSTRIDE + b*PSTRIDE;
        num += base[n];
        den += base[32];
    }
    out[idx] = num / den;
}

// ---------------------------------------------------------------------------
extern "C" void kernel_launch(void* const* d_in, const int* in_sizes, int n_in,
                              void* d_out, int out_size)
{
    const float* X   = (const float*)d_in[0];
    const float* t   = (const float*)d_in[1];
    const float* Mu0 = (const float*)d_in[2];
    const float* Mu1 = (const float*)d_in[3];
    const float* S0  = (const float*)d_in[4];
    const float* S1  = (const float*)d_in[5];
    const float* Lam = (const float*)d_in[6];
    float* out = (float*)d_out;

    const int smem_bytes = (4*PAIRS_PER_CTA*ND + 2*PAIRS_PER_CTA
                            + GROUPS*NB*REDPAD) * (int)sizeof(float); // ~136 KB
    cudaFuncSetAttribute(main_kernel,
                         cudaFuncAttributeMaxDynamicSharedMemorySize, smem_bytes);

    precompute_kernel<<<NN0, NN1>>>(t, Mu0, Mu1, S0, S1);
    main_kernel<<<NCHUNK, THREADS, smem_bytes>>>(X, Lam);
    reduce_kernel<<<(NB*ND + 255)/256, 256>>>(out);
}